// round 17
// baseline (speedup 1.0000x reference)
#include <cuda_runtime.h>
#include <cuda_bf16.h>
#include <cstdint>
#include <math.h>

typedef unsigned long long ull;

#define Bn 16
#define Dn 256
#define Ln 200
#define Tn 1000
#define TT 16
#define NB 63            // ceil(1000/16)
#define KW 832           // K layout: [0..7]=wc, [8]=bias, [9..15]=0, [16+4l+q], [816..831]=0
#define WS 208           // w_s plane stride (floats)

#define OFF_MEAN ((size_t)0)
#define OFF_LOG  ((size_t)4096000)
#define OFF_FM   ((size_t)8192000)
#define OFF_FL   ((size_t)8208000)
#define OFF_W    ((size_t)8208016)

// ---------------- device scratch ----------------
__device__ float g_sk[Bn*Ln];
__device__ int   g_plen[Bn];
__device__ int   g_flen[Bn];
__device__ float g_phonT[(size_t)Bn*Ln*Dn];          // [b][l][d] f32 (conv)
__device__ unsigned short g_phbf_hi[(size_t)Bn*Ln*Dn];  // bf16 split of phonT
__device__ unsigned short g_phbf_lo[(size_t)Bn*Ln*Dn];
__device__ unsigned short g_lwbf_hi[4*Dn*Dn];        // LwT [q][d][dd] bf16
__device__ unsigned short g_lwbf_lo[4*Dn*Dn];
__device__ float g_hw[(size_t)Bn*Ln*8];
__device__ float g_hc[(size_t)Bn*Ln*8];
__device__ float g_Ceff[2*8*3*Dn];
__device__ float g_beff[2*8*3];
__device__ unsigned short g_wbf_hi[(size_t)Bn*1024*KW];  // W' [b][t(1024)][k]
__device__ unsigned short g_wbf_lo[(size_t)Bn*1024*KW];
__device__ unsigned short g_pbf_hi[(size_t)Bn*Dn*KW];    // P'T [b][d][k]
__device__ unsigned short g_pbf_lo[(size_t)Bn*Dn*KW];
__device__ unsigned short g_yhi[(size_t)Bn*Tn*Dn];   // bf16 hi of y
__device__ unsigned short g_ylo[(size_t)Bn*Tn*Dn];
__device__ unsigned short g_woThi[512*256];          // bf16 WoT [n][k]
__device__ unsigned short g_woTlo[512*256];

__device__ __forceinline__ float silu_f(float x){ return __fdividef(x, 1.f + __expf(-x)); }

__device__ __forceinline__ uint32_t smem_u32(const void* p){
  uint32_t a;
  asm("{ .reg .u64 t; cvta.to.shared.u64 t, %1; cvt.u32.u64 %0, t; }" : "=r"(a) : "l"(p));
  return a;
}
__device__ __forceinline__ void bf_split(float v, unsigned short& h, unsigned short& l){
  __nv_bfloat16 hb = __float2bfloat16(v);
  h = __bfloat16_as_ushort(hb);
  l = __bfloat16_as_ushort(__float2bfloat16(v - __bfloat162float(hb)));
}

// ---------------- mma.sync / cp.async helpers ----------------
__device__ __forceinline__ void ldsm4(uint32_t& r0, uint32_t& r1, uint32_t& r2, uint32_t& r3,
                                      uint32_t addr){
  asm volatile("ldmatrix.sync.aligned.m8n8.x4.shared.b16 {%0,%1,%2,%3}, [%4];"
    : "=r"(r0), "=r"(r1), "=r"(r2), "=r"(r3) : "r"(addr));
}
__device__ __forceinline__ void mma16816(float* d, const uint32_t* a, uint32_t b0, uint32_t b1){
  asm volatile("mma.sync.aligned.m16n8k16.row.col.f32.bf16.bf16.f32 "
    "{%0,%1,%2,%3},{%4,%5,%6,%7},{%8,%9},{%0,%1,%2,%3};"
    : "+f"(d[0]), "+f"(d[1]), "+f"(d[2]), "+f"(d[3])
    : "r"(a[0]), "r"(a[1]), "r"(a[2]), "r"(a[3]), "r"(b0), "r"(b1));
}
#define CP16(dst,src) asm volatile("cp.async.cg.shared.global [%0],[%1],16;" :: "r"(dst), "l"(src) : "memory")
#define CP_COMMIT()   asm volatile("cp.async.commit_group;" ::: "memory")
#define CP_WAIT1()    asm volatile("cp.async.wait_group 1;" ::: "memory")
#define CP_WAIT0()    asm volatile("cp.async.wait_group 0;" ::: "memory")

// ================= K_PRE =================
// 0..895 transpose(+bf16) | 896..943 ceff | 944..945 beff | 946..961 setup |
// 962..963 WoT | 964..979 P'-extra | 980..1235 LwT split-transpose
__global__ void k_pre(const float* __restrict__ dur, const float* __restrict__ phon,
                      const float* __restrict__ Cw, const float* __restrict__ Wpw,
                      const float* __restrict__ Cc, const float* __restrict__ Wpc,
                      const float* __restrict__ bpw, const float* __restrict__ cbw,
                      const float* __restrict__ bpc, const float* __restrict__ cbc,
                      const float* __restrict__ Wo, const float* __restrict__ Lw,
                      const float* __restrict__ Lcm, const float* __restrict__ lbw,
                      const float* __restrict__ lbc,
                      float* __restrict__ out){
  __shared__ float tile[32][33];
  __shared__ float cs[Dn];
  __shared__ int sfl;
  int bi = blockIdx.x, tid = threadIdx.x;

  if (bi < 896){
    int l0 = (bi%7)*32, d0 = ((bi/7)%8)*32, b = bi/56;
    int tx = tid&31, ty = tid>>5;
    #pragma unroll
    for (int r=0;r<4;r++){
      int dy = d0+ty+8*r, lx = l0+tx;
      tile[ty+8*r][tx] = (lx<Ln) ? phon[((size_t)b*Dn+dy)*Ln+lx] : 0.f;
    }
    __syncthreads();
    #pragma unroll
    for (int r=0;r<4;r++){
      int ly = l0+ty+8*r, dx = d0+tx;
      if (ly<Ln){
        float v = tile[tx][ty+8*r];
        size_t idx = ((size_t)b*Ln+ly)*Dn+dx;
        g_phonT[idx] = v;
        unsigned short h,l; bf_split(v,h,l);
        g_phbf_hi[idx]=h; g_phbf_lo[idx]=l;
      }
    }
  } else if (bi < 944){
    int idx = bi-896;
    int o = idx&7, k = (idx>>3)%3, which = idx/24;
    const float* C = which? Cc : Cw;
    const float* W = which? Wpc : Wpw;
    cs[tid] = C[(o*Dn+tid)*3+k];
    __syncthreads();
    float acc=0.f;
    #pragma unroll 8
    for (int d=0; d<Dn; d++)
      acc = fmaf(cs[d], W[d*Dn+tid], acc);
    g_Ceff[((which*8+o)*3+k)*Dn + tid] = acc;
  } else if (bi < 946){
    int which = bi-944;
    const float* C = which? Cc: Cw; const float* bp = which? bpc : bpw; const float* cb = which? cbc : cbw;
    int wp = tid>>5, lane = tid&31;
    for (int pr=wp; pr<24; pr+=8){
      int o = pr/3, var = pr%3;
      int k0 = (var==0)?1:0, k1 = (var==2)?1:2;
      float acc = 0.f;
      #pragma unroll
      for (int i=0;i<8;i++){
        int d = lane + 32*i;
        float bv = bp[d];
        for (int k=k0;k<=k1;k++) acc = fmaf(C[(o*Dn+d)*3+k], bv, acc);
      }
      #pragma unroll
      for (int off=16;off;off>>=1) acc += __shfl_xor_sync(0xffffffffu, acc, off);
      if (lane==0) g_beff[(which*8+o)*3+var] = acc + cb[o];
    }
  } else if (bi < 962){
    int b = bi-946;
    float* s = &tile[0][0];
    if (tid < Ln) s[tid] = dur[b*Ln+tid];
    __syncthreads();
    if (tid == 0){
      float acc = 0.f; int plen = 0;
      for (int l=0;l<Ln;l++){ g_sk[b*Ln+l]=acc; float d=s[l]; acc+=d; if (d>0.f) plen=l+1; }
      g_plen[b]=plen;
      int fl = (int)rintf(acc); fl = fl<0?0:(fl>Tn?Tn:fl);
      g_flen[b]=fl; sfl=fl;
      out[OFF_FL + b] = (float)fl;
    }
    __syncthreads();
    int fl = sfl;
    for (int t=tid;t<Tn;t+=256) out[OFF_FM + (size_t)b*Tn + t] = (t<fl)?1.f:0.f;
  } else if (bi < 964){
    // WoT hi/lo split
    int n = (bi-962)*256 + tid;
    for (int kc=0;kc<32;kc++){
      __align__(16) unsigned short h8[8];
      __align__(16) unsigned short l8[8];
      #pragma unroll
      for (int j=0;j<8;j++){
        float w = Wo[(size_t)(kc*8+j)*512 + n];
        bf_split(w, h8[j], l8[j]);
      }
      *(uint4*)&g_woThi[n*256 + kc*8] = *(uint4*)h8;
      *(uint4*)&g_woTlo[n*256 + kc*8] = *(uint4*)l8;
    }
  } else if (bi < 980){
    // P' head rows: k=0..7 = Lc, k=8 = lbw+lbc, 9..15 = 0; pad 816..831 = 0
    int b = bi-964;
    size_t base = ((size_t)b*Dn + tid)*KW;
    #pragma unroll
    for (int i=0;i<8;i++){
      unsigned short h,l; bf_split(Lcm[i*Dn+tid], h, l);
      g_pbf_hi[base+i]=h; g_pbf_lo[base+i]=l;
    }
    {
      unsigned short h,l; bf_split(lbw[tid]+lbc[tid], h, l);
      g_pbf_hi[base+8]=h; g_pbf_lo[base+8]=l;
    }
    for (int k=9;k<16;k++){ g_pbf_hi[base+k]=0; g_pbf_lo[base+k]=0; }
    for (int k=816;k<KW;k++){ g_pbf_hi[base+k]=0; g_pbf_lo[base+k]=0; }
  } else {
    // LwT split-transpose: LwT[q][d][dd] = Lw[q*256+dd][d]
    int idx = bi-980;            // 0..255
    int q = idx>>6;
    int rem = idx&63;
    int dd0 = (rem&7)*32;
    int d0  = (rem>>3)*32;
    int tx = tid&31, ty = tid>>5;
    #pragma unroll
    for (int r=0;r<4;r++)
      tile[ty+8*r][tx] = Lw[(size_t)(q*256 + dd0+ty+8*r)*Dn + d0+tx];
    __syncthreads();
    #pragma unroll
    for (int r=0;r<4;r++){
      float v = tile[tx][ty+8*r];
      unsigned short h,l; bf_split(v,h,l);
      size_t o = ((size_t)q*Dn + d0+ty+8*r)*Dn + dd0+tx;
      g_lwbf_hi[o]=h; g_lwbf_lo[o]=l;
    }
  }
}

// ================= K_MIDP: conv (0..399) + P' GEMM (400..911) in one launch =================
#define KP_ST 49152
#define KP_SMEM 98304

__global__ __launch_bounds__(256,2) void k_midp(){
  extern __shared__ float smf[];
  char* smc = (char*)smf;
  int bi = blockIdx.x, tid = threadIdx.x;

  if (bi < 400){
    // ---- conv+silu -> h_w, h_c ----
    float* xs = smf;
    int b = bi/25, l0 = (bi%25)*8;
    for (int i=tid; i<10*Dn; i+=256){
      int r = i>>8, dp = i&255, col = l0-1+r;
      xs[r*Dn+dp] = (col>=0 && col<Ln) ? g_phonT[((size_t)b*Ln+col)*Dn+dp] : 0.f;
    }
    __syncthreads();
    int warp = tid>>5, lane = tid&31;
    int l = l0 + warp;
    int plen = g_plen[b];
    for (int idx=0; idx<16; idx++){
      int which = idx>>3, o = idx&7;
      const float* ce = g_Ceff + ((which*8+o)*3)*Dn;
      float acc = 0.f;
      for (int i=lane; i<3*Dn; i+=32){
        int k = i>>8, dp = i&255;
        acc = fmaf(ce[k*Dn+dp], xs[((l-l0)+k)*Dn+dp], acc);
      }
      #pragma unroll
      for (int off=16; off; off>>=1) acc += __shfl_xor_sync(0xffffffffu, acc, off);
      if (lane==0){
        int var = (l==0)?0:((l==Ln-1)?2:1);
        float h = silu_f(acc + g_beff[(which*8+o)*3+var]);
        h = (l < plen) ? h : 0.f;
        float* dst = which ? g_hc : g_hw;
        dst[((size_t)b*Ln+l)*8 + o] = h;
      }
    }
    return;
  }

  // ---- P' GEMM: P'[d][16+4l+q] = LwT[q] @ phonT[b] ----
  uint32_t sb = smem_u32(smc);
  int wid = tid>>5, lane = tid&31;
  int pidx = bi - 400;                 // 0..511
  int mtile = pidx & 1;
  int ntile = (pidx>>1) & 3;
  int bz = pidx >> 3;                  // 0..63
  int b = bz>>2, q = bz&3;

  float acc[2][4][4];
  #pragma unroll
  for (int mt=0;mt<2;mt++)
    #pragma unroll
    for (int ng=0;ng<4;ng++){ acc[mt][ng][0]=0.f; acc[mt][ng][1]=0.f; acc[mt][ng][2]=0.f; acc[mt][ng][3]=0.f; }

  int m0 = (wid&3)*32, n0 = (wid>>2)*32;

  const uint4* aH_g = ((const uint4*)g_lwbf_hi) + (size_t)(q*Dn + mtile*128)*32;
  const uint4* aL_g = ((const uint4*)g_lwbf_lo) + (size_t)(q*Dn + mtile*128)*32;
  const uint4* bH_g = ((const uint4*)g_phbf_hi) + (size_t)(b*Ln)*32;
  const uint4* bL_g = ((const uint4*)g_phbf_lo) + (size_t)(b*Ln)*32;

  int srow = tid>>3, sch = tid&7;
  uint32_t soff = (uint32_t)(srow*128 + ((sch ^ (srow&7))<<4));

  #define KP_ISSUE(c, s) do{                                              \
    uint32_t base_ = sb + (uint32_t)(s)*KP_ST;                            \
    _Pragma("unroll")                                                     \
    for (int i_=0;i_<4;i_++){                                             \
      uint32_t off_ = soff + (uint32_t)(i_*32*128);                       \
      size_t g_ = (size_t)(srow + i_*32)*32 + (c)*8 + sch;                \
      CP16(base_ + off_,         aH_g + g_);                              \
      CP16(base_ + 16384 + off_, aL_g + g_);                              \
    }                                                                     \
    _Pragma("unroll")                                                     \
    for (int i_=0;i_<2;i_++){                                             \
      uint32_t off_ = soff + (uint32_t)(i_*32*128);                       \
      int lr_ = ntile*64 + srow + i_*32; if (lr_ > Ln-1) lr_ = Ln-1;      \
      size_t g_ = (size_t)lr_*32 + (c)*8 + sch;                           \
      CP16(base_ + 32768 + off_, bH_g + g_);                              \
      CP16(base_ + 40960 + off_, bL_g + g_);                              \
    }                                                                     \
    CP_COMMIT();                                                          \
  }while(0)

  KP_ISSUE(0, 0);
  for (int c=0;c<4;c++){
    int s = c & 1;
    if (c+1 < 4){ KP_ISSUE(c+1, s^1); CP_WAIT1(); }
    else        { CP_WAIT0(); }
    __syncthreads();
    uint32_t stb = sb + (uint32_t)s*KP_ST;
    #pragma unroll
    for (int kk=0;kk<4;kk++){
      uint32_t aH[2][4], aL[2][4];
      #pragma unroll
      for (int mt=0;mt<2;mt++){
        int arow = m0 + mt*16 + (lane&15);
        uint32_t aoff = (uint32_t)(arow*128 + (((kk*2 + (lane>>4)) ^ (arow&7))<<4));
        ldsm4(aH[mt][0],aH[mt][1],aH[mt][2],aH[mt][3], stb + aoff);
        ldsm4(aL[mt][0],aL[mt][1],aL[mt][2],aL[mt][3], stb + 16384 + aoff);
      }
      #pragma unroll
      for (int g2=0;g2<2;g2++){
        int nrow = n0 + g2*16 + ((lane>>4)<<3) + (lane&7);
        uint32_t boff = (uint32_t)(nrow*128 + (((kk*2 + ((lane>>3)&1)) ^ (nrow&7))<<4));
        uint32_t bh0,bh1,bh2,bh3, bl0,bl1,bl2,bl3;
        ldsm4(bh0,bh1,bh2,bh3, stb + 32768 + boff);
        ldsm4(bl0,bl1,bl2,bl3, stb + 40960 + boff);
        #pragma unroll
        for (int mt=0;mt<2;mt++){
          mma16816(acc[mt][g2*2],   aH[mt], bh0, bh1);
          mma16816(acc[mt][g2*2],   aL[mt], bh0, bh1);
          mma16816(acc[mt][g2*2],   aH[mt], bl0, bl1);
          mma16816(acc[mt][g2*2+1], aH[mt], bh2, bh3);
          mma16816(acc[mt][g2*2+1], aL[mt], bh2, bh3);
          mma16816(acc[mt][g2*2+1], aH[mt], bl2, bl3);
        }
      }
    }
    __syncthreads();
  }

  // epilogue: P'[b][d][16 + 4*col + q] (guard col < 200)
  #pragma unroll
  for (int mt=0;mt<2;mt++){
    #pragma unroll
    for (int ng=0;ng<4;ng++){
      int col = ntile*64 + n0 + ng*8 + 2*(lane&3);
      if (col < Ln){
        #pragma unroll
        for (int half=0;half<2;half++){
          int d = mtile*128 + m0 + mt*16 + (lane>>2) + half*8;
          size_t base = ((size_t)(b*Dn) + d)*KW + 16 + q;
          unsigned short h0,l0,h1,l1;
          bf_split(acc[mt][ng][half*2+0], h0, l0);
          bf_split(acc[mt][ng][half*2+1], h1, l1);
          g_pbf_hi[base + 4*col]     = h0;
          g_pbf_lo[base + 4*col]     = l0;
          g_pbf_hi[base + 4*(col+1)] = h1;
          g_pbf_lo[base + 4*(col+1)] = l1;
        }
      }
    }
  }
}

// ================= K_MAIN: phases 1-2 with fused W' export =================
// dyn smem (floats): w_s [64][WS=208] 0..13312 | sk 13312..13512 | bc 13512..13912 |
//                    wc 13912..14040 | prm 14040..14106
#define SMEM_BYTES 56424

__global__ __launch_bounds__(256,3) void k_main(
  const float* __restrict__ dur,
  const float* __restrict__ Mw, const float* __restrict__ mbw,
  const float* __restrict__ Mc, const float* __restrict__ mbc,
  float* __restrict__ out)
{
  extern __shared__ float sm[];
  float* w_s  = sm;
  float* sk_s = sm + 13312;
  float* bc_s = sm + 13512;
  float* wc_s = sm + 13912;
  float* prm  = sm + 14040;

  int b = blockIdx.y;
  int t0 = blockIdx.x * TT;
  int tid = threadIdx.x;
  int plen = g_plen[b], flen = g_flen[b];
  bool active = (t0 < flen);

  if (active){
    if (tid < 40)      prm[tid] = Mw[tid];
    else if (tid < 44) prm[tid] = mbw[tid-40];
    else if (tid < 64) prm[tid] = Mc[tid-44];
    else if (tid < 66) prm[tid] = mbc[tid-64];
    __syncthreads();

    // ---- phase 1 ----
    if (tid < Ln){
      int l = tid;
      float dv = dur[b*Ln + l];
      float sk = g_sk[b*Ln + l];
      sk_s[l] = sk;
      const float* hwp = g_hw + ((size_t)b*Ln+l)*8;
      const float* hcp = g_hc + ((size_t)b*Ln+l)*8;
      float bw[4], bc[2];
      #pragma unroll
      for (int q=0;q<4;q++){
        float a = prm[40+q] + dv*prm[4+q];
        #pragma unroll
        for (int j=0;j<8;j++) a = fmaf(hwp[j], prm[(2+j)*4+q], a);
        bw[q]=a;
      }
      #pragma unroll
      for (int p=0;p<2;p++){
        float a = prm[64+p] + dv*prm[46+p];
        #pragma unroll
        for (int j=0;j<8;j++) a = fmaf(hcp[j], prm[44+(2+j)*2+p], a);
        bc[p]=a;
      }
      bc_s[2*l]   = bc[0];
      bc_s[2*l+1] = bc[1];
      bool lv = l < plen;
      #pragma unroll
      for (int t=0;t<TT;t++){
        int tt = t0+t;
        float4 av = {0.f,0.f,0.f,0.f};
        if (lv && tt < flen){
          float S = (float)(tt+1) - sk;
          av.x = silu_f(fmaf(S, prm[0], bw[0]));
          av.y = silu_f(fmaf(S, prm[1], bw[1]));
          av.z = silu_f(fmaf(S, prm[2], bw[2]));
          av.w = silu_f(fmaf(S, prm[3], bw[3]));
        }
        float* wp_ = w_s + (t*4)*WS + l;
        wp_[0]      = av.x;
        wp_[WS]     = av.y;
        wp_[2*WS]   = av.z;
        wp_[3*WS]   = av.w;
      }
    }
    __syncthreads();

    // ---- phase 2: softmax + f32 w out + bf16 W' export (vectorized) + wc reduce ----
    {
      int wp = tid>>5, lane = tid&31;
      float mc0 = prm[44], mc1 = prm[45];
      const size_t qs = (size_t)Tn*Ln;
      for (int t=wp; t<TT; t+=8){
        int tt = t0+t;
        if (tt >= Tn) continue;
        size_t wb = OFF_W + ((size_t)(b*4)*Tn + tt)*Ln;
        size_t rw = ((size_t)(b*1024)+tt)*KW;
        if (tt >= flen){
          for (int l=lane; l<Ln; l+=32){
            out[wb+l]=0.f; out[wb+qs+l]=0.f; out[wb+2*qs+l]=0.f; out[wb+3*qs+l]=0.f;
          }
          for (int k=lane; k<KW; k+=32){ g_wbf_hi[rw+k]=0; g_wbf_lo[rw+k]=0; }
          if (lane<8) wc_s[t*8+lane]=0.f;
          continue;
        }
        const float* wp0 = w_s + (t*4)*WS;
        float4 wv[7];
        float m0=-3e38f,m1=-3e38f,m2=-3e38f,m3=-3e38f;
        #pragma unroll
        for (int i=0;i<7;i++){
          int l = lane + 32*i;
          if (l < plen){
            wv[i].x = wp0[l];
            wv[i].y = wp0[WS+l];
            wv[i].z = wp0[2*WS+l];
            wv[i].w = wp0[3*WS+l];
            m0=fmaxf(m0,wv[i].x); m1=fmaxf(m1,wv[i].y); m2=fmaxf(m2,wv[i].z); m3=fmaxf(m3,wv[i].w);
          }
        }
        #pragma unroll
        for (int off=16;off;off>>=1){
          m0=fmaxf(m0,__shfl_xor_sync(0xffffffffu,m0,off));
          m1=fmaxf(m1,__shfl_xor_sync(0xffffffffu,m1,off));
          m2=fmaxf(m2,__shfl_xor_sync(0xffffffffu,m2,off));
          m3=fmaxf(m3,__shfl_xor_sync(0xffffffffu,m3,off));
        }
        float s0=0.f,s1=0.f,s2=0.f,s3=0.f;
        #pragma unroll
        for (int i=0;i<7;i++){
          int l = lane + 32*i;
          if (l < plen){
            wv[i].x=__expf(wv[i].x-m0); wv[i].y=__expf(wv[i].y-m1);
            wv[i].z=__expf(wv[i].z-m2); wv[i].w=__expf(wv[i].w-m3);
            s0+=wv[i].x; s1+=wv[i].y; s2+=wv[i].z; s3+=wv[i].w;
          }
        }
        #pragma unroll
        for (int off=16;off;off>>=1){
          s0+=__shfl_xor_sync(0xffffffffu,s0,off);
          s1+=__shfl_xor_sync(0xffffffffu,s1,off);
          s2+=__shfl_xor_sync(0xffffffffu,s2,off);
          s3+=__shfl_xor_sync(0xffffffffu,s3,off);
        }
        float i0=__fdividef(1.f,s0), i1=__fdividef(1.f,s1), i2=__fdividef(1.f,s2), i3=__fdividef(1.f,s3);
        float Sb = (float)(tt+1);
        float r0=0.f,r1=0.f,r2=0.f,r3=0.f,r4=0.f,r5=0.f,r6=0.f,r7=0.f;
        #pragma unroll
        for (int i=0;i<7;i++){
          int l = lane + 32*i;
          if (l < plen){
            float4 v; v.x=wv[i].x*i0; v.y=wv[i].y*i1; v.z=wv[i].z*i2; v.w=wv[i].w*i3;
            out[wb+l]=v.x; out[wb+qs+l]=v.y; out[wb+2*qs+l]=v.z; out[wb+3*qs+l]=v.w;
            ushort4 hv, lv2;
            bf_split(v.x, hv.x, lv2.x);
            bf_split(v.y, hv.y, lv2.y);
            bf_split(v.z, hv.z, lv2.z);
            bf_split(v.w, hv.w, lv2.w);
            *(ushort4*)&g_wbf_hi[rw + 16 + 4*l] = hv;
            *(ushort4*)&g_wbf_lo[rw + 16 + 4*l] = lv2;
            float S = Sb - sk_s[l];
            float cx = silu_f(fmaf(S, mc0, bc_s[2*l]));
            float cy = silu_f(fmaf(S, mc1, bc_s[2*l+1]));
            r0=fmaf(v.x,cx,r0); r1=fmaf(v.x,cy,r1);
            r2=fmaf(v.y,cx,r2); r3=fmaf(v.y,cy,r3);
            r4=fmaf(v.z,cx,r4); r5=fmaf(v.z,cy,r5);
            r6=fmaf(v.w,cx,r6); r7=fmaf(v.w,cy,r7);
          } else if (l < Ln){
            out[wb+l]=0.f; out[wb+qs+l]=0.f; out[wb+2*qs+l]=0.f; out[wb+3*qs+l]=0.f;
            ushort4 z4; z4.x=0; z4.y=0; z4.z=0; z4.w=0;
            *(ushort4*)&g_wbf_hi[rw + 16 + 4*l] = z4;
            *(ushort4*)&g_wbf_lo[rw + 16 + 4*l] = z4;
          }
        }
        #pragma unroll
        for (int off=16;off;off>>=1){
          r0+=__shfl_xor_sync(0xffffffffu,r0,off); r1+=__shfl_xor_sync(0xffffffffu,r1,off);
          r2+=__shfl_xor_sync(0xffffffffu,r2,off); r3+=__shfl_xor_sync(0xffffffffu,r3,off);
          r4+=__shfl_xor_sync(0xffffffffu,r4,off); r5+=__shfl_xor_sync(0xffffffffu,r5,off);
          r6+=__shfl_xor_sync(0xffffffffu,r6,off); r7+=__shfl_xor_sync(0xffffffffu,r7,off);
        }
        if (lane==0){
          wc_s[t*8+0]=r0; wc_s[t*8+1]=r1; wc_s[t*8+2]=r2; wc_s[t*8+3]=r3;
          wc_s[t*8+4]=r4; wc_s[t*8+5]=r5; wc_s[t*8+6]=r6; wc_s[t*8+7]=r7;
        }
      }
    }
    __syncthreads();

    // ---- tail: W' head k=0..15 (wc, bias, pad) + pad k=816..831 ----
    for (int x=tid; x<TT*32; x+=256){
      int t = x>>5, j = x&31;
      int tt = t0+t;
      if (tt >= Tn) continue;
      size_t rw = ((size_t)(b*1024)+tt)*KW;
      if (j < 16){
        float v = 0.f;
        if (j < 8)      v = wc_s[t*8+j];
        else if (j == 8) v = (tt < flen) ? 1.f : 0.f;
        unsigned short h,lo; bf_split(v,h,lo);
        g_wbf_hi[rw+j]=h; g_wbf_lo[rw+j]=lo;
      } else {
        int k = 800 + j;   // 816..831
        g_wbf_hi[rw+k]=0; g_wbf_lo[rw+k]=0;
      }
    }
  } else {
    // inactive: zero w planes + zero W' rows
    int wp = tid>>5, lane = tid&31;
    const size_t qs = (size_t)Tn*Ln;
    for (int t=wp; t<TT; t+=8){
      int tt = t0+t;
      if (tt >= Tn) continue;
      size_t wb = OFF_W + ((size_t)(b*4)*Tn + tt)*Ln;
      for (int l=lane; l<Ln; l+=32){
        out[wb+l]=0.f; out[wb+qs+l]=0.f; out[wb+2*qs+l]=0.f; out[wb+3*qs+l]=0.f;
      }
    }
    for (int t=0;t<TT;t++){
      int tt = t0+t;
      if (tt >= Tn) break;
      size_t rw = ((size_t)(b*1024)+tt)*KW;
      for (int k=tid;k<KW;k+=256){ g_wbf_hi[rw+k]=0; g_wbf_lo[rw+k]=0; }
    }
  }
}

// ================= K_COMB: Y = W' @ P'  (cp.async DB, per-b chunk count) =================
#define KC_ST 49152
#define KC_SMEM 98304

__global__ __launch_bounds__(256,2) void k_comb(){
  extern __shared__ float smf[];
  char* smc = (char*)smf;
  uint32_t sb = smem_u32(smc);
  int tid = threadIdx.x, wid = tid>>5, lane = tid&31;
  int mtile = blockIdx.x, ntile = blockIdx.y, b = blockIdx.z;

  if (mtile*128 >= g_flen[b]){
    uint4 z; z.x=0u; z.y=0u; z.z=0u; z.w=0u;
    #pragma unroll
    for (int i=0;i<4;i++){
      int lin = i*256 + tid;
      int r = lin>>3, ch = lin&7;
      int t = mtile*128 + r;
      if (t < Tn){
        size_t row = (size_t)b*Tn + t;
        ((uint4*)(g_yhi + row*Dn + ntile*64))[ch] = z;
        ((uint4*)(g_ylo + row*Dn + ntile*64))[ch] = z;
      }
    }
    return;
  }

  int nch = (16 + 4*g_plen[b] + 63) >> 6;   // 10..13 live chunks

  float acc[2][4][4];
  #pragma unroll
  for (int mt=0;mt<2;mt++)
    #pragma unroll
    for (int ng=0;ng<4;ng++){ acc[mt][ng][0]=0.f; acc[mt][ng][1]=0.f; acc[mt][ng][2]=0.f; acc[mt][ng][3]=0.f; }

  int m0 = (wid&3)*32, n0 = (wid>>2)*32;

  const uint4* gwh = (const uint4*)(g_wbf_hi + ((size_t)(b*1024) + (size_t)mtile*128)*KW);
  const uint4* gwl = (const uint4*)(g_wbf_lo + ((size_t)(b*1024) + (size_t)mtile*128)*KW);
  const uint4* gph = (const uint4*)(g_pbf_hi + ((size_t)(b*Dn) + (size_t)ntile*64)*KW);
  const uint4* gpl = (const uint4*)(g_pbf_lo + ((size_t)(b*Dn) + (size_t)ntile*64)*KW);
  const int rs = KW/8;   // 104

  int srow = tid>>3, sch = tid&7;
  uint32_t soff = (uint32_t)(srow*128 + ((sch ^ (srow&7))<<4));

  #define KC_ISSUE(c, s) do{                                              \
    uint32_t base_ = sb + (uint32_t)(s)*KC_ST;                            \
    _Pragma("unroll")                                                     \
    for (int i_=0;i_<4;i_++){                                             \
      uint32_t off_ = soff + (uint32_t)(i_*32*128);                       \
      size_t g_ = (size_t)(srow + i_*32)*rs + (c)*8 + sch;                \
      CP16(base_ + off_,          gwh + g_);                              \
      CP16(base_ + 16384 + off_,  gwl + g_);                              \
    }                                                                     \
    _Pragma("unroll")                                                     \
    for (int i_=0;i_<2;i_++){                                             \
      uint32_t off_ = soff + (uint32_t)(i_*32*128);                       \
      size_t g_ = (size_t)(srow + i_*32)*rs + (c)*8 + sch;                \
      CP16(base_ + 32768 + off_,  gph + g_);                              \
      CP16(base_ + 40960 + off_,  gpl + g_);                              \
    }                                                                     \
    CP_COMMIT();                                                          \
  }while(0)

  KC_ISSUE(0, 0);
  for (int c=0;c<nch;c++){
    int s = c & 1;
    if (c+1 < nch){ KC_ISSUE(c+1, s^1); CP_WAIT1(); }
    else          { CP_WAIT0(); }
    __syncthreads();
    uint32_t stb = sb + (uint32_t)s*KC_ST;
    #pragma unroll
    for (int kk=0;kk<4;kk++){
      uint32_t aH[2][4], aL[2][4];
      #pragma unroll
      for (int mt=0;mt<2;mt++){
        int arow = m0 + mt*16 + (lane&15);
        uint32_t aoff = (uint32_t)(arow*128 + (((kk*2 + (lane>>4)) ^ (arow&7))<<4));
        ldsm4(aH[mt][0],aH[mt][1],aH[mt][2],aH[mt][3], stb + aoff);
        ldsm4(aL[mt][0],aL[mt][1],aL[mt][2],aL[mt][3], stb + 16384 + aoff);
      }
      #pragma unroll
      for (int g2=0;g2<2;g2++){
        int nrow = n0 + g2*16 + ((lane>>4)<<3) + (lane&7);
        uint32_t boff = (uint32_t)(nrow*128 + (((kk*2 + ((lane>>3)&1)) ^ (nrow&7))<<4));
        uint32_t bh0,bh1,bh2,bh3, bl0,bl1,bl2,bl3;
        ldsm4(bh0,bh1,bh2,bh3, stb + 32768 + boff);
        ldsm4(bl0,bl1,bl2,bl3, stb + 40960 + boff);
        #pragma unroll
        for (int mt=0;mt<2;mt++){
          mma16816(acc[mt][g2*2],   aH[mt], bh0, bh1);
          mma16816(acc[mt][g2*2],   aL[mt], bh0, bh1);
          mma16816(acc[mt][g2*2],   aH[mt], bl0, bl1);
          mma16816(acc[mt][g2*2+1], aH[mt], bh2, bh3);
          mma16816(acc[mt][g2*2+1], aL[mt], bh2, bh3);
          mma16816(acc[mt][g2*2+1], aH[mt], bl2, bl3);
        }
      }
    }
    __syncthreads();
  }

  #pragma unroll
  for (int mt=0;mt<2;mt++){
    #pragma unroll
    for (int ng=0;ng<4;ng++){
      int d = ntile*64 + n0 + ng*8 + (lane&3)*2;
      #pragma unroll
      for (int half=0;half<2;half++){
        int t = mtile*128 + m0 + mt*16 + (lane>>2) + half*8;
        if (t < Tn){
          size_t row = (size_t)b*Tn + t;
          unsigned short h0,l0,h1,l1;
          bf_split(acc[mt][ng][half*2+0], h0, l0);
          bf_split(acc[mt][ng][half*2+1], h1, l1);
          ushort2 hh; hh.x=h0; hh.y=h1;
          ushort2 ll; ll.x=l0; ll.y=l1;
          *(ushort2*)&g_yhi[row*Dn + d] = hh;
          *(ushort2*)&g_ylo[row*Dn + d] = ll;
        }
      }
    }
  }
}

// ================= K_OUT: out = y @ Wo + bo  (cp.async double-buffered) =================
#define KO_ST 49152
#define KO_SMEM 98304

__global__ __launch_bounds__(256,2) void k_out(const float* __restrict__ bo,
                                               float* __restrict__ out){
  extern __shared__ float smf[];
  char* smc = (char*)smf;
  uint32_t sb = smem_u32(smc);
  int tid = threadIdx.x, wid = tid>>5, lane = tid&31;
  int mtile = blockIdx.x, ntile = blockIdx.y;

  {
    int mstart = mtile*128;
    int b0 = mstart/Tn, b1 = (mstart+127)/Tn;
    int t_start = mstart - b0*Tn;
    bool dead = (t_start >= g_flen[b0]) && (b1==b0 || g_flen[b1]<=0);
    if (dead){
      int r = tid & 127;
      int m = mtile*128 + r;
      int b = m/Tn, t = m - b*Tn;
      size_t plane = (ntile<4)?OFF_MEAN:OFF_LOG;
      int colbase = ntile*64 - ((ntile>=4)?256:0);
      const float* bop = bo + ntile*64;
      for (int i = tid>>7; i<64; i+=2)
        out[plane + ((size_t)(b*Dn + colbase + i))*Tn + t] = bop[i];
      return;
    }
  }

  float acc[2][4][4];
  #pragma unroll
  for (int mt=0;mt<2;mt++)
    #pragma unroll
    for (int ng=0;ng<4;ng++){ acc[mt][ng][0]=0.f; acc[mt][ng][1]=0.f; acc[mt][ng][2]=0.f; acc[mt][ng][3]=0.f; }

  int m0 = (wid&3)*32, n0 = (wid>>2)*32;

  const uint4* aH_g = (const uint4*)(g_yhi + (size_t)(mtile*128)*Dn);
  const uint4* aL_g = (const uint4*)(g_ylo + (size_t)(mtile*128)*Dn);
  const uint4* bH_g = (const uint4*)(g_woThi + (size_t)(ntile*64)*256);
  const uint4* bL_g = (const uint4*)(g_woTlo + (size_t)(ntile*64)*256);

  int srow = tid>>3, sch = tid&7;
  uint32_t soff = (uint32_t)(srow*128 + ((sch ^ (srow&7))<<4));

  #define KO_ISSUE(c, s) do{                                              \
    uint32_t base_ = sb + (uint32_t)(s)*KO_ST;                            \
    _Pragma("unroll")                                                     \
    for (int i_=0;i_<4;i_++){                                             \
      uint32_t off_ = soff + (uint32_t)(i_*32*128);                       \
      size_t g_ = (size_t)(srow + i_*32)*32 + (c)*8 + sch;                \
      CP16(base_ + off_,         aH_g + g_);                              \
      CP16(base_ + 16384 + off_, aL_g + g_);                              \
    }                                                                     \
    _Pragma("unroll")                                                     \
    for (int i_=0;i_<2;i_++){                                             \
      uint32_t off_ = soff + (uint32_t)(i_*32*128);                       \
      size_t g_ = (size_t)(srow + i_*32)*32 + (c)*8 + sch;                \
      CP16(base_ + 32768 + off_, bH_g + g_);                              \
      CP16(base_ + 40960 + off_, bL_g + g_);                              \
    }                                                                     \
    CP_COMMIT();                                                          \
  }while(0)

  KO_ISSUE(0, 0);
  for (int c=0;c<4;c++){
    int s = c & 1;
    if (c+1 < 4){ KO_ISSUE(c+1, s^1); CP_WAIT1(); }
    else        { CP_WAIT0(); }
    __syncthreads();
    uint32_t stb = sb + (uint32_t)s*KO_ST;
    #pragma unroll
    for (int kk=0;kk<4;kk++){
      uint32_t aH[2][4], aL[2][4];
      #pragma unroll
      for (int mt=0;mt<2;mt++){
        int arow = m0 + mt*16 + (lane&15);
        uint32_t aoff = (uint32_t)(arow*128 + (((kk*2 + (lane>>4)) ^ (arow&7))<<4));
        ldsm4(aH[mt][0],aH[mt][1],aH[mt][2],aH[mt][3], stb + aoff);
        ldsm4(aL[mt][0],aL[mt][1],aL[mt][2],aL[mt][3], stb + 16384 + aoff);
      }
      #pragma unroll
      for (int g2=0;g2<2;g2++){
        int nrow = n0 + g2*16 + ((lane>>4)<<3) + (lane&7);
        uint32_t boff = (uint32_t)(nrow*128 + (((kk*2 + ((lane>>3)&1)) ^ (nrow&7))<<4));
        uint32_t bh0,bh1,bh2,bh3, bl0,bl1,bl2,bl3;
        ldsm4(bh0,bh1,bh2,bh3, stb + 32768 + boff);
        ldsm4(bl0,bl1,bl2,bl3, stb + 40960 + boff);
        #pragma unroll
        for (int mt=0;mt<2;mt++){
          mma16816(acc[mt][g2*2],   aH[mt], bh0, bh1);
          mma16816(acc[mt][g2*2],   aL[mt], bh0, bh1);
          mma16816(acc[mt][g2*2],   aH[mt], bl0, bl1);
          mma16816(acc[mt][g2*2+1], aH[mt], bh2, bh3);
          mma16816(acc[mt][g2*2+1], aL[mt], bh2, bh3);
          mma16816(acc[mt][g2*2+1], aH[mt], bl2, bl3);
        }
      }
    }
    __syncthreads();
  }

  {
    size_t plane = (ntile < 4) ? OFF_MEAN : OFF_LOG;
    int colbase = ntile*64 - ((ntile>=4)?256:0);
    const float* bop = bo + ntile*64;
    #pragma unroll
    for (int mt=0;mt<2;mt++){
      #pragma unroll
      for (int ng=0;ng<4;ng++){
        int cin = n0 + ng*8 + 2*(lane&3);
        float b0v = bop[cin], b1v = bop[cin+1];
        #pragma unroll
        for (int half=0;half<2;half++){
          int m_g = mtile*128 + m0 + mt*16 + (lane>>2) + half*8;
          int b = m_g / Tn;
          int t = m_g - b*Tn;
          size_t base = plane + ((size_t)(b*Dn + colbase + cin))*Tn + t;
          out[base]      = acc[mt][ng][half*2+0] + b0v;
          out[base + Tn] = acc[mt][ng][half*2+1] + b1v;
        }
      }
    }
  }
}

// ---------------- launcher ----------------
extern "C" void kernel_launch(void* const* d_in, const int* in_sizes, int n_in,
                              void* d_out, int out_size){
  (void)in_sizes; (void)n_in; (void)out_size;
  const float* dur = (const float*)d_in[0];
  const float* phon= (const float*)d_in[1];
  const float* Wpw = (const float*)d_in[3];
  const float* bpw = (const float*)d_in[4];
  const float* Cw  = (const float*)d_in[5];
  const float* cbw = (const float*)d_in[6];
  const float* Mw  = (const float*)d_in[7];
  const float* mbw = (const float*)d_in[8];
  const float* Lw  = (const float*)d_in[9];
  const float* lbw = (const float*)d_in[10];
  const float* Wpc = (const float*)d_in[11];
  const float* bpc = (const float*)d_in[12];
  const float* Cc  = (const float*)d_in[13];
  const float* cbc = (const float*)d_in[14];
  const float* Mc  = (const float*)d_in[15];
  const float* mbc = (const float*)d_in[16];
  const float* Lcm = (const float*)d_in[17];
  const float* lbc = (const float*)d_in[18];
  const float* Wo  = (const float*)d_in[19];
  const float* bo  = (const float*)d_in[20];
  float* out = (float*)d_out;

  cudaFuncSetAttribute((const void*)k_main, cudaFuncAttributeMaxDynamicSharedMemorySize,
                       SMEM_BYTES);
  cudaFuncSetAttribute((const void*)k_midp, cudaFuncAttributeMaxDynamicSharedMemorySize,
                       KP_SMEM);
  cudaFuncSetAttribute((const void*)k_comb, cudaFuncAttributeMaxDynamicSharedMemorySize,
                       KC_SMEM);
  cudaFuncSetAttribute((const void*)k_out, cudaFuncAttributeMaxDynamicSharedMemorySize,
                       KO_SMEM);

  k_pre<<<1236,256>>>(dur, phon, Cw, Wpw, Cc, Wpc, bpw, cbw, bpc, cbc, Wo, Lw, Lcm, lbw, lbc, out);
  k_midp<<<912,256,KP_SMEM>>>();
  k_main<<<dim3(NB,Bn),256,SMEM_BYTES>>>(dur,Mw,mbw,Mc,mbc,out);
  k_comb<<<dim3(8,4,Bn),256,KC_SMEM>>>();
  k_out<<<dim3(125,8),256,KO_SMEM>>>(bo,out);
}